// round 7
// baseline (speedup 1.0000x reference)
#include <cuda_runtime.h>
#include <cstdint>

// StructureTensorEffect, B=4, C=3, H=W=1024.
// Separable form: s_u = Gx*Sy, s_v = Sx*Gy with per-batch-constant fractional
// stencils. sigma in [0.5,2.5) => JP = floor(sigma) in {0,1,2}, JM = -JP-1.
// Templated on JP so all stencil offsets are compile-time constants.
//
// R7 = R2 with (a) phase-1 sliding 5-tap row set (20 live regs instead of a
// 7-float4 rolling window) and (b) __launch_bounds__(256,4) for 4 blocks/SM.
//
// Phase 1 (vertical): 5-tap register set, reuse 2 taps/row, 3 fresh LDG.128.
// Phase 2 (horizontal): 4 px/thread, 3 LDS.128 per array per channel,
//   16B lane stride (conflict-free). Border: exact 8-tap bilinear fallback.

#define Wd 1024
#define Hd 1024
#define TX 128
#define TY 16
#define HX 4
#define SW (TX + 2*HX)            // 136 floats per smem row
#define NTH 256
#define NSTRIP (SW/4)             // 34 float4 strips
#define CHUNK 8
#define NCHUNK (TY/CHUNK)         // 2
#define NVTASK (NSTRIP*NCHUNK*3)  // 204
#define HW (Hd*Wd)
#define SMEM_FLOATS (3*TY*SW)     // per array
#define SMEM_BYTES (2*SMEM_FLOATS*4)

__device__ __forceinline__ int clampi(int v, int lo, int hi) {
    return min(max(v, lo), hi);
}

// Exact per-pixel path replicating reference clip semantics (border only).
__device__ __noinline__ void exact_pixel(const float* __restrict__ xb, float s,
                                         int gx, int gy,
                                         float& A, float& Bv, float& Cv) {
    const float OU[8] = {-1.f,-1.f,-1.f, 0.f, 0.f, 1.f, 1.f, 1.f};
    const float OV[8] = {-1.f, 0.f, 1.f,-1.f, 1.f,-1.f, 0.f, 1.f};
    const float KU[8] = {-0.25f,-0.5f,-0.25f, 0.f, 0.f, 0.25f, 0.5f, 0.25f};
    const float KV[8] = {-0.25f, 0.f, 0.25f,-0.5f, 0.5f,-0.25f, 0.f, 0.25f};
    float su[3] = {0.f,0.f,0.f}, sv[3] = {0.f,0.f,0.f};
    #pragma unroll
    for (int t = 0; t < 8; ++t) {
        float px = (float)gx + OU[t] * s;
        float py = (float)gy + OV[t] * s;
        float x0f = floorf(px), y0f = floorf(py);
        float fx = px - x0f, fy = py - y0f;
        int x0 = clampi((int)x0f, 0, Wd - 1);
        int x1 = min(x0 + 1, Wd - 1);
        int y0 = clampi((int)y0f, 0, Hd - 1);
        int y1 = min(y0 + 1, Hd - 1);
        float w00 = (1.f - fx) * (1.f - fy);
        float w01 = fx * (1.f - fy);
        float w10 = (1.f - fx) * fy;
        float w11 = fx * fy;
        #pragma unroll
        for (int c = 0; c < 3; ++c) {
            const float* p = xb + (size_t)c * HW;
            float bil = w00 * __ldg(&p[y0 * Wd + x0]) + w01 * __ldg(&p[y0 * Wd + x1])
                      + w10 * __ldg(&p[y1 * Wd + x0]) + w11 * __ldg(&p[y1 * Wd + x1]);
            su[c] += KU[t] * bil;
            sv[c] += KV[t] * bil;
        }
    }
    A = 0.f; Bv = 0.f; Cv = 0.f;
    #pragma unroll
    for (int c = 0; c < 3; ++c) {
        float l = (c == 0) ? 100.f : 1.f;
        float a = su[c] * l, b = sv[c] * l;
        A += a * a; Bv += b * b; Cv += a * b;
    }
}

template<int JP>
__device__ __forceinline__ void run_tile(const float* __restrict__ xb, float s,
                                         float* __restrict__ smS,
                                         float* __restrict__ smG,
                                         float* __restrict__ out,
                                         int b, int bx0, int by0, int tid) {
    // weights: fp = s - JP in [0,1); fm = 1 - fp
    const float fp  = s - (float)JP;
    const float wp0 = 0.5f * (1.f - fp);
    const float wp1 = 0.5f * fp;
    const float wm0 = wp1;            // 0.5*(1-fm)
    const float wm1 = wp0;            // 0.5*fm

    // ---------------- Phase 1: vertical stencil -> smem ----------------
    if (tid < NVTASK) {
        const int c     = tid / (NSTRIP * NCHUNK);
        const int rem   = tid - c * (NSTRIP * NCHUNK);
        const int chunk = rem / NSTRIP;
        const int strip = rem - chunk * NSTRIP;

        const float* plane = xb + (size_t)c * HW;
        int gx0 = bx0 - HX + strip * 4;
        gx0 = clampi(gx0, 0, Wd - 4);

        const int ybase = by0 + chunk * CHUNK;

        // Sliding 5-tap set for row y: {y-JP-1, y-JP, y, y+JP, y+JP+1}.
        #define LDROW(yy) __ldg((const float4*)(plane + \
                  (size_t)clampi((yy), 0, Hd - 1) * Wd + gx0))
        float4 t0 = LDROW(ybase - JP - 1);
        float4 t1 = LDROW(ybase - JP);
        float4 t2 = LDROW(ybase);
        float4 t3 = LDROW(ybase + JP);
        float4 t4 = LDROW(ybase + JP + 1);

        float* sSrow = smS + (size_t)(c * TY + chunk * CHUNK) * SW + strip * 4;
        float* sGrow = smG + (size_t)(c * TY + chunk * CHUNK) * SW + strip * 4;

        #pragma unroll
        for (int j = 0; j < CHUNK; ++j) {
            float4 vs, vg;
            {
                float mpx = wm0 * t0.x + wm1 * t1.x;
                float mpy = wm0 * t0.y + wm1 * t1.y;
                float mpz = wm0 * t0.z + wm1 * t1.z;
                float mpw = wm0 * t0.w + wm1 * t1.w;
                float ppx = wp0 * t3.x + wp1 * t4.x;
                float ppy = wp0 * t3.y + wp1 * t4.y;
                float ppz = wp0 * t3.z + wp1 * t4.z;
                float ppw = wp0 * t3.w + wp1 * t4.w;
                vs.x = t2.x + mpx + ppx;  vg.x = ppx - mpx;
                vs.y = t2.y + mpy + ppy;  vg.y = ppy - mpy;
                vs.z = t2.z + mpz + ppz;  vg.z = ppz - mpz;
                vs.w = t2.w + mpw + ppw;  vg.w = ppw - mpw;
            }
            *(float4*)(sSrow + (size_t)j * SW) = vs;
            *(float4*)(sGrow + (size_t)j * SW) = vg;

            if (j < CHUNK - 1) {
                const int yn = ybase + j + 1;
                t0 = t1;                      // y-JP-1 <- old y-JP
                t3 = t4;                      // y+JP   <- old y+JP+1
                t1 = LDROW(yn - JP);
                t2 = LDROW(yn);
                t4 = LDROW(yn + JP + 1);
            }
        }
        #undef LDROW
    }
    __syncthreads();

    // ---------------- Phase 2: horizontal stencil + quadratics ----------------
    const int tx5 = tid & 31;        // col group
    const int tyh = tid >> 5;        // 0..7
    const int xl  = tx5 * 4;         // local output col 0..124
    const int r0  = tyh * 2;         // two rows per thread

    float accA[2][4], accB[2][4], accC[2][4];
    #pragma unroll
    for (int rr = 0; rr < 2; ++rr)
        #pragma unroll
        for (int i = 0; i < 4; ++i) { accA[rr][i] = 0.f; accB[rr][i] = 0.f; accC[rr][i] = 0.f; }

    constexpr int dM = 3 - JP;   // JM + 4
    constexpr int dP = 4 + JP;

    #pragma unroll
    for (int c = 0; c < 3; ++c) {
        const float l = (c == 0) ? 100.f : 1.f;
        #pragma unroll
        for (int rr = 0; rr < 2; ++rr) {
            const int lr = r0 + rr;
            const float* Sp = smS + (size_t)(c * TY + lr) * SW + xl;   // window base (= pixel - 4)
            const float* Gp = smG + (size_t)(c * TY + lr) * SW + xl;
            float4 a0 = *(const float4*)(Sp);
            float4 a1 = *(const float4*)(Sp + 4);
            float4 a2 = *(const float4*)(Sp + 8);
            float4 b0 = *(const float4*)(Gp);
            float4 b1 = *(const float4*)(Gp + 4);
            float4 b2 = *(const float4*)(Gp + 8);
            float sw[12] = {a0.x,a0.y,a0.z,a0.w, a1.x,a1.y,a1.z,a1.w, a2.x,a2.y,a2.z,a2.w};
            float gw[12] = {b0.x,b0.y,b0.z,b0.w, b1.x,b1.y,b1.z,b1.w, b2.x,b2.y,b2.z,b2.w};
            #pragma unroll
            for (int i = 0; i < 4; ++i) {
                float su = wp0 * sw[i + dP] + wp1 * sw[i + dP + 1]
                         - wm0 * sw[i + dM] - wm1 * sw[i + dM + 1];
                float sv = gw[i + 4]
                         + wm0 * gw[i + dM] + wm1 * gw[i + dM + 1]
                         + wp0 * gw[i + dP] + wp1 * gw[i + dP + 1];
                float a  = l * su;
                float bq = l * sv;
                accA[rr][i] += a * a;
                accB[rr][i] += bq * bq;
                accC[rr][i] += a * bq;
            }
        }
    }

    // ---------------- Output ----------------
    float* out0 = out + ((size_t)b * 3 + 0) * HW;
    float* out1 = out + ((size_t)b * 3 + 1) * HW;
    float* out2 = out + ((size_t)b * 3 + 2) * HW;
    const int gxg = bx0 + xl;
    const bool xint = (gxg >= 3) && (gxg + 3 <= Wd - 4);

    #pragma unroll
    for (int rr = 0; rr < 2; ++rr) {
        const int gy = by0 + r0 + rr;
        const bool yint = (gy >= 3) && (gy <= Hd - 4);
        const size_t o = (size_t)gy * Wd + gxg;
        if (xint && yint) {
            *(float4*)(out0 + o) = make_float4(accA[rr][0], accA[rr][1], accA[rr][2], accA[rr][3]);
            *(float4*)(out1 + o) = make_float4(accB[rr][0], accB[rr][1], accB[rr][2], accB[rr][3]);
            *(float4*)(out2 + o) = make_float4(accC[rr][0], accC[rr][1], accC[rr][2], accC[rr][3]);
        } else {
            #pragma unroll
            for (int i = 0; i < 4; ++i) {
                int gx = gxg + i;
                float A = accA[rr][i], Bv = accB[rr][i], Cv = accC[rr][i];
                if (!(yint && gx >= 3 && gx <= Wd - 4)) {
                    exact_pixel(xb, s, gx, gy, A, Bv, Cv);
                }
                out0[o + i] = A;
                out1[o + i] = Bv;
                out2[o + i] = Cv;
            }
        }
    }
}

__global__ __launch_bounds__(NTH, 4)
void st7_kernel(const float* __restrict__ x, const float* __restrict__ sigma,
                float* __restrict__ out) {
    extern __shared__ float sm[];
    float* smS = sm;
    float* smG = sm + SMEM_FLOATS;

    const int b   = blockIdx.z;
    const int bx0 = blockIdx.x * TX;
    const int by0 = blockIdx.y * TY;
    const int tid = threadIdx.x;

    const float s = __ldg(&sigma[b]);
    const int jp = clampi((int)floorf(s), 0, 2);
    const float* xb = x + (size_t)b * 3 * HW;

    if (jp == 0)      run_tile<0>(xb, s, smS, smG, out, b, bx0, by0, tid);
    else if (jp == 1) run_tile<1>(xb, s, smS, smG, out, b, bx0, by0, tid);
    else              run_tile<2>(xb, s, smS, smG, out, b, bx0, by0, tid);
}

extern "C" void kernel_launch(void* const* d_in, const int* in_sizes, int n_in,
                              void* d_out, int out_size) {
    const float* x     = (const float*)d_in[0];
    const float* sigma = (const float*)d_in[1];
    float* out = (float*)d_out;
    int B = in_sizes[1];

    static_assert(SMEM_BYTES == 52224, "smem size");
    cudaFuncSetAttribute(st7_kernel, cudaFuncAttributeMaxDynamicSharedMemorySize, SMEM_BYTES);

    dim3 grid(Wd / TX, Hd / TY, B);
    st7_kernel<<<grid, NTH, SMEM_BYTES>>>(x, sigma, out);
}

// round 8
// speedup vs baseline: 1.0684x; 1.0684x over previous
#include <cuda_runtime.h>
#include <cstdint>

// StructureTensorEffect, B=4, C=3, H=W=1024.
// Separable: s_u = Gx*Sy, s_v = Sx*Gy, per-batch-constant stencils.
// sigma in [0.5,2.5) => JP = floor(sigma) in {0,1,2}; templated on JP.
//
// R8: warp-specialized pipeline. 384 threads: tid<128 = producers (vertical
// stencil -> smem), tid>=128 = consumers (horizontal stencil + quadratics).
// Tile 128x32 = 4 chunks of 8 rows, double-buffered smem; producers fill
// chunk k+1 while consumers eat chunk k. Border: exact 8-tap fallback.

#define Wd 1024
#define Hd 1024
#define HW (Hd*Wd)
#define TX 128
#define TY 32
#define CH 8                      // rows per chunk
#define NCHK (TY/CH)              // 4
#define HX 4
#define SW (TX + 2*HX)            // 136
#define NTH 384
#define NPROD 128
#define NSTRIP (SW/4)             // 34
#define NPTASK (NSTRIP*3)         // 102
#define BUF_FLOATS (2*3*CH*SW)    // 6528 per array (S or G)
#define SMEM_BYTES (2*BUF_FLOATS*4)   // 52224

__device__ __forceinline__ int clampi(int v, int lo, int hi) {
    return min(max(v, lo), hi);
}

// Exact per-pixel path replicating reference clip semantics (border only).
__device__ __noinline__ void exact_pixel(const float* __restrict__ xb, float s,
                                         int gx, int gy,
                                         float& A, float& Bv, float& Cv) {
    const float OU[8] = {-1.f,-1.f,-1.f, 0.f, 0.f, 1.f, 1.f, 1.f};
    const float OV[8] = {-1.f, 0.f, 1.f,-1.f, 1.f,-1.f, 0.f, 1.f};
    const float KU[8] = {-0.25f,-0.5f,-0.25f, 0.f, 0.f, 0.25f, 0.5f, 0.25f};
    const float KV[8] = {-0.25f, 0.f, 0.25f,-0.5f, 0.5f,-0.25f, 0.f, 0.25f};
    float su[3] = {0.f,0.f,0.f}, sv[3] = {0.f,0.f,0.f};
    #pragma unroll
    for (int t = 0; t < 8; ++t) {
        float px = (float)gx + OU[t] * s;
        float py = (float)gy + OV[t] * s;
        float x0f = floorf(px), y0f = floorf(py);
        float fx = px - x0f, fy = py - y0f;
        int x0 = clampi((int)x0f, 0, Wd - 1);
        int x1 = min(x0 + 1, Wd - 1);
        int y0 = clampi((int)y0f, 0, Hd - 1);
        int y1 = min(y0 + 1, Hd - 1);
        float w00 = (1.f - fx) * (1.f - fy);
        float w01 = fx * (1.f - fy);
        float w10 = (1.f - fx) * fy;
        float w11 = fx * fy;
        #pragma unroll
        for (int c = 0; c < 3; ++c) {
            const float* p = xb + (size_t)c * HW;
            float bil = w00 * __ldg(&p[y0 * Wd + x0]) + w01 * __ldg(&p[y0 * Wd + x1])
                      + w10 * __ldg(&p[y1 * Wd + x0]) + w11 * __ldg(&p[y1 * Wd + x1]);
            su[c] += KU[t] * bil;
            sv[c] += KV[t] * bil;
        }
    }
    A = 0.f; Bv = 0.f; Cv = 0.f;
    #pragma unroll
    for (int c = 0; c < 3; ++c) {
        float l = (c == 0) ? 100.f : 1.f;
        float a = su[c] * l, b = sv[c] * l;
        A += a * a; Bv += b * b; Cv += a * b;
    }
}

// Produce chunk CK (8 rows) of vertical-stencil results into buf (CK&1).
// win holds rows (tile-relative) with row r at index (r+JP+1) % WIN.
template<int JP, int CK>
__device__ __forceinline__ void produce(float4 (&win)[2*JP+3],
                                        const float* __restrict__ plane,
                                        int gx0, int by0,
                                        float* __restrict__ sSc,   // chunk base + strip*4
                                        float* __restrict__ sGc,
                                        float wm0, float wm1, float wp0, float wp1) {
    constexpr int WIN = 2 * JP + 3;
    #define LDROW(yy) __ldg((const float4*)(plane + \
              (size_t)clampi(by0 + (yy), 0, Hd - 1) * Wd + gx0))
    #pragma unroll
    for (int j = 0; j < CH; ++j) {
        constexpr int dummy = 0; (void)dummy;
        const int y = CK * CH + j;               // compile-time per unrolled iter
        win[(y + WIN - 1) % WIN] = LDROW(y + JP + 1);
        float4 m0 = win[(y)              % WIN];
        float4 m1 = win[(y + 1)          % WIN];
        float4 ce = win[(y + JP + 1)     % WIN];
        float4 p0 = win[(y + 2 * JP + 1) % WIN];
        float4 p1 = win[(y + 2 * JP + 2) % WIN];
        float4 vs, vg;
        {
            float mpx = wm0 * m0.x + wm1 * m1.x;
            float mpy = wm0 * m0.y + wm1 * m1.y;
            float mpz = wm0 * m0.z + wm1 * m1.z;
            float mpw = wm0 * m0.w + wm1 * m1.w;
            float ppx = wp0 * p0.x + wp1 * p1.x;
            float ppy = wp0 * p0.y + wp1 * p1.y;
            float ppz = wp0 * p0.z + wp1 * p1.z;
            float ppw = wp0 * p0.w + wp1 * p1.w;
            vs.x = ce.x + mpx + ppx;  vg.x = ppx - mpx;
            vs.y = ce.y + mpy + ppy;  vg.y = ppy - mpy;
            vs.z = ce.z + mpz + ppz;  vg.z = ppz - mpz;
            vs.w = ce.w + mpw + ppw;  vg.w = ppw - mpw;
        }
        *(float4*)(sSc + (size_t)j * SW) = vs;
        *(float4*)(sGc + (size_t)j * SW) = vg;
    }
    #undef LDROW
}

// Consume chunk CK: horizontal stencil + quadratics + store (4 px/thread).
template<int JP, int CK>
__device__ __forceinline__ void consume(const float* __restrict__ smS,
                                        const float* __restrict__ smG,
                                        const float* __restrict__ xb, float s,
                                        float* __restrict__ out,
                                        int b, int bx0, int by0, int ctid,
                                        float wm0, float wm1, float wp0, float wp1) {
    const int cg    = ctid & 31;     // 0..31 col groups (x4 = 128 px)
    const int rowin = ctid >> 5;     // 0..7
    const int xl    = cg * 4;
    const int gy    = by0 + CK * CH + rowin;
    constexpr int buf = CK & 1;
    constexpr int dM = 3 - JP;
    constexpr int dP = 4 + JP;

    float aA[4] = {0.f,0.f,0.f,0.f};
    float aB[4] = {0.f,0.f,0.f,0.f};
    float aC[4] = {0.f,0.f,0.f,0.f};

    #pragma unroll
    for (int c = 0; c < 3; ++c) {
        const float l = (c == 0) ? 100.f : 1.f;
        const float* Sp = smS + (size_t)(((buf * 3 + c) * CH) + rowin) * SW + xl;
        const float* Gp = smG + (size_t)(((buf * 3 + c) * CH) + rowin) * SW + xl;
        float4 a0 = *(const float4*)(Sp);
        float4 a1 = *(const float4*)(Sp + 4);
        float4 a2 = *(const float4*)(Sp + 8);
        float4 b0 = *(const float4*)(Gp);
        float4 b1 = *(const float4*)(Gp + 4);
        float4 b2 = *(const float4*)(Gp + 8);
        float sw[12] = {a0.x,a0.y,a0.z,a0.w, a1.x,a1.y,a1.z,a1.w, a2.x,a2.y,a2.z,a2.w};
        float gw[12] = {b0.x,b0.y,b0.z,b0.w, b1.x,b1.y,b1.z,b1.w, b2.x,b2.y,b2.z,b2.w};
        #pragma unroll
        for (int i = 0; i < 4; ++i) {
            float su = wp0 * sw[i + dP] + wp1 * sw[i + dP + 1]
                     - wm0 * sw[i + dM] - wm1 * sw[i + dM + 1];
            float sv = gw[i + 4]
                     + wm0 * gw[i + dM] + wm1 * gw[i + dM + 1]
                     + wp0 * gw[i + dP] + wp1 * gw[i + dP + 1];
            float a  = l * su;
            float bq = l * sv;
            aA[i] += a * a;
            aB[i] += bq * bq;
            aC[i] += a * bq;
        }
    }

    float* out0 = out + ((size_t)b * 3 + 0) * HW;
    float* out1 = out + ((size_t)b * 3 + 1) * HW;
    float* out2 = out + ((size_t)b * 3 + 2) * HW;
    const int gxg = bx0 + xl;
    const bool xint = (gxg >= 3) && (gxg + 3 <= Wd - 4);
    const bool yint = (gy >= 3) && (gy <= Hd - 4);
    const size_t o = (size_t)gy * Wd + gxg;
    if (xint && yint) {
        *(float4*)(out0 + o) = make_float4(aA[0], aA[1], aA[2], aA[3]);
        *(float4*)(out1 + o) = make_float4(aB[0], aB[1], aB[2], aB[3]);
        *(float4*)(out2 + o) = make_float4(aC[0], aC[1], aC[2], aC[3]);
    } else {
        #pragma unroll
        for (int i = 0; i < 4; ++i) {
            int gx = gxg + i;
            float A = aA[i], Bv = aB[i], Cv = aC[i];
            if (!(yint && gx >= 3 && gx <= Wd - 4)) {
                exact_pixel(xb, s, gx, gy, A, Bv, Cv);
            }
            out0[o + i] = A;
            out1[o + i] = Bv;
            out2[o + i] = Cv;
        }
    }
}

template<int JP>
__device__ __forceinline__ void run_tile(const float* __restrict__ xb, float s,
                                         float* __restrict__ smS,
                                         float* __restrict__ smG,
                                         float* __restrict__ out,
                                         int b, int bx0, int by0, int tid) {
    constexpr int WIN = 2 * JP + 3;
    const float fp  = s - (float)JP;
    const float wp0 = 0.5f * (1.f - fp);
    const float wp1 = 0.5f * fp;
    const float wm0 = wp1;
    const float wm1 = wp0;

    const bool pact = (tid < NPTASK);          // producer-active
    const bool cons = (tid >= NPROD);          // consumer

    // Producer setup + window prime.
    float4 win[WIN];
    const float* plane = xb;
    float* pS = smS; float* pG = smG;
    int gx0 = 0;
    int pch = 0, strip = 0;
    if (pact) {
        pch   = tid / NSTRIP;
        strip = tid - pch * NSTRIP;
        plane = xb + (size_t)pch * HW;
        gx0   = clampi(bx0 - HX + strip * 4, 0, Wd - 4);
        #pragma unroll
        for (int k = 0; k < WIN - 1; ++k) {
            int yy = -JP - 1 + k;
            win[k] = __ldg((const float4*)(plane +
                     (size_t)clampi(by0 + yy, 0, Hd - 1) * Wd + gx0));
        }
    }
    // Per-(buf,ch) chunk bases for this producer's strip.
    // S(buf,ch,row) = smS + ((buf*3+ch)*CH + row)*SW
    const int pbase0 = ((0 * 3 + pch) * CH) * SW + strip * 4;  // buf 0
    const int pbase1 = ((1 * 3 + pch) * CH) * SW + strip * 4;  // buf 1

    // Pipeline: prologue fill chunk 0, then overlap.
    if (pact) produce<JP, 0>(win, plane, gx0, by0, pS + pbase0, pG + pbase0, wm0, wm1, wp0, wp1);
    __syncthreads();
    if (pact)      produce<JP, 1>(win, plane, gx0, by0, pS + pbase1, pG + pbase1, wm0, wm1, wp0, wp1);
    else if (cons) consume<JP, 0>(smS, smG, xb, s, out, b, bx0, by0, tid - NPROD, wm0, wm1, wp0, wp1);
    __syncthreads();
    if (pact)      produce<JP, 2>(win, plane, gx0, by0, pS + pbase0, pG + pbase0, wm0, wm1, wp0, wp1);
    else if (cons) consume<JP, 1>(smS, smG, xb, s, out, b, bx0, by0, tid - NPROD, wm0, wm1, wp0, wp1);
    __syncthreads();
    if (pact)      produce<JP, 3>(win, plane, gx0, by0, pS + pbase1, pG + pbase1, wm0, wm1, wp0, wp1);
    else if (cons) consume<JP, 2>(smS, smG, xb, s, out, b, bx0, by0, tid - NPROD, wm0, wm1, wp0, wp1);
    __syncthreads();
    if (cons)      consume<JP, 3>(smS, smG, xb, s, out, b, bx0, by0, tid - NPROD, wm0, wm1, wp0, wp1);
}

__global__ __launch_bounds__(NTH)
void st8_kernel(const float* __restrict__ x, const float* __restrict__ sigma,
                float* __restrict__ out) {
    extern __shared__ float sm[];
    float* smS = sm;
    float* smG = sm + BUF_FLOATS;

    const int b   = blockIdx.z;
    const int bx0 = blockIdx.x * TX;
    const int by0 = blockIdx.y * TY;
    const int tid = threadIdx.x;

    const float s = __ldg(&sigma[b]);
    const int jp = clampi((int)floorf(s), 0, 2);
    const float* xb = x + (size_t)b * 3 * HW;

    if (jp == 0)      run_tile<0>(xb, s, smS, smG, out, b, bx0, by0, tid);
    else if (jp == 1) run_tile<1>(xb, s, smS, smG, out, b, bx0, by0, tid);
    else              run_tile<2>(xb, s, smS, smG, out, b, bx0, by0, tid);
}

extern "C" void kernel_launch(void* const* d_in, const int* in_sizes, int n_in,
                              void* d_out, int out_size) {
    const float* x     = (const float*)d_in[0];
    const float* sigma = (const float*)d_in[1];
    float* out = (float*)d_out;
    int B = in_sizes[1];

    static_assert(SMEM_BYTES == 52224, "smem size");
    cudaFuncSetAttribute(st8_kernel, cudaFuncAttributeMaxDynamicSharedMemorySize, SMEM_BYTES);

    dim3 grid(Wd / TX, Hd / TY, B);                 // (8, 32, 4) = 1024 blocks
    st8_kernel<<<grid, NTH, SMEM_BYTES>>>(x, sigma, out);
}

// round 9
// speedup vs baseline: 1.6132x; 1.5099x over previous
#include <cuda_runtime.h>
#include <cstdint>

// StructureTensorEffect, B=4, C=3, H=W=1024.
// Separable: s_u = Gx*Sy, s_v = Sx*Gy, per-batch-constant stencils.
// sigma in [0.5,2.5) => JP = floor(sigma) in {0,1,2}; templated on JP.
//
// R9 = R2 dataflow with halved per-thread state and doubled threads:
//   512 threads/block, phase 2 = 1 row x 4 px per thread (12 accumulators),
//   phase 1 = 4-row chunks (408 active tasks). Target: 64 regs w/o spill,
//   2 blocks/SM = 32 warps.

#define Wd 1024
#define Hd 1024
#define TX 128
#define TY 16
#define HX 4
#define SW (TX + 2*HX)            // 136 floats per smem row
#define NTH 512
#define NSTRIP (SW/4)             // 34 float4 strips
#define CHUNK 4
#define NCHUNK (TY/CHUNK)         // 4
#define NVTASK (NSTRIP*NCHUNK*3)  // 408
#define HW (Hd*Wd)
#define SMEM_FLOATS (3*TY*SW)     // per array
#define SMEM_BYTES (2*SMEM_FLOATS*4)

__device__ __forceinline__ int clampi(int v, int lo, int hi) {
    return min(max(v, lo), hi);
}

// Exact per-pixel path replicating reference clip semantics (border only).
__device__ __noinline__ void exact_pixel(const float* __restrict__ xb, float s,
                                         int gx, int gy,
                                         float& A, float& Bv, float& Cv) {
    const float OU[8] = {-1.f,-1.f,-1.f, 0.f, 0.f, 1.f, 1.f, 1.f};
    const float OV[8] = {-1.f, 0.f, 1.f,-1.f, 1.f,-1.f, 0.f, 1.f};
    const float KU[8] = {-0.25f,-0.5f,-0.25f, 0.f, 0.f, 0.25f, 0.5f, 0.25f};
    const float KV[8] = {-0.25f, 0.f, 0.25f,-0.5f, 0.5f,-0.25f, 0.f, 0.25f};
    float su[3] = {0.f,0.f,0.f}, sv[3] = {0.f,0.f,0.f};
    #pragma unroll
    for (int t = 0; t < 8; ++t) {
        float px = (float)gx + OU[t] * s;
        float py = (float)gy + OV[t] * s;
        float x0f = floorf(px), y0f = floorf(py);
        float fx = px - x0f, fy = py - y0f;
        int x0 = clampi((int)x0f, 0, Wd - 1);
        int x1 = min(x0 + 1, Wd - 1);
        int y0 = clampi((int)y0f, 0, Hd - 1);
        int y1 = min(y0 + 1, Hd - 1);
        float w00 = (1.f - fx) * (1.f - fy);
        float w01 = fx * (1.f - fy);
        float w10 = (1.f - fx) * fy;
        float w11 = fx * fy;
        #pragma unroll
        for (int c = 0; c < 3; ++c) {
            const float* p = xb + (size_t)c * HW;
            float bil = w00 * __ldg(&p[y0 * Wd + x0]) + w01 * __ldg(&p[y0 * Wd + x1])
                      + w10 * __ldg(&p[y1 * Wd + x0]) + w11 * __ldg(&p[y1 * Wd + x1]);
            su[c] += KU[t] * bil;
            sv[c] += KV[t] * bil;
        }
    }
    A = 0.f; Bv = 0.f; Cv = 0.f;
    #pragma unroll
    for (int c = 0; c < 3; ++c) {
        float l = (c == 0) ? 100.f : 1.f;
        float a = su[c] * l, b = sv[c] * l;
        A += a * a; Bv += b * b; Cv += a * b;
    }
}

template<int JP>
__device__ __forceinline__ void run_tile(const float* __restrict__ xb, float s,
                                         float* __restrict__ smS,
                                         float* __restrict__ smG,
                                         float* __restrict__ out,
                                         int b, int bx0, int by0, int tid) {
    // weights: fp = s - JP in [0,1); fm = 1 - fp
    const float fp  = s - (float)JP;
    const float wp0 = 0.5f * (1.f - fp);
    const float wp1 = 0.5f * fp;
    const float wm0 = wp1;            // 0.5*(1-fm)
    const float wm1 = wp0;            // 0.5*fm

    // ---------------- Phase 1: vertical stencil -> smem ----------------
    if (tid < NVTASK) {
        const int c     = tid / (NSTRIP * NCHUNK);
        const int rem   = tid - c * (NSTRIP * NCHUNK);
        const int chunk = rem / NSTRIP;
        const int strip = rem - chunk * NSTRIP;

        const float* plane = xb + (size_t)c * HW;
        int gx0 = bx0 - HX + strip * 4;
        gx0 = clampi(gx0, 0, Wd - 4);

        const int ybase = by0 + chunk * CHUNK;

        constexpr int WIN = 2 * JP + 3;
        float4 win[WIN];
        #pragma unroll
        for (int r = -JP - 1; r <= JP; ++r) {
            int gy = clampi(ybase + r, 0, Hd - 1);
            win[r + JP + 1] = __ldg((const float4*)(plane + (size_t)gy * Wd + gx0));
        }

        float* sSrow = smS + (size_t)(c * TY + chunk * CHUNK) * SW + strip * 4;
        float* sGrow = smG + (size_t)(c * TY + chunk * CHUNK) * SW + strip * 4;

        #pragma unroll
        for (int j = 0; j < CHUNK; ++j) {
            int gy = clampi(ybase + j + JP + 1, 0, Hd - 1);
            win[(j + 2 * JP + 2) % WIN] = __ldg((const float4*)(plane + (size_t)gy * Wd + gx0));

            float4 m0 = win[(j)              % WIN];
            float4 m1 = win[(j + 1)          % WIN];
            float4 ce = win[(j + JP + 1)     % WIN];
            float4 p0 = win[(j + 2 * JP + 1) % WIN];
            float4 p1 = win[(j + 2 * JP + 2) % WIN];

            float4 vs, vg;
            {
                float mpx = wm0 * m0.x + wm1 * m1.x;
                float mpy = wm0 * m0.y + wm1 * m1.y;
                float mpz = wm0 * m0.z + wm1 * m1.z;
                float mpw = wm0 * m0.w + wm1 * m1.w;
                float ppx = wp0 * p0.x + wp1 * p1.x;
                float ppy = wp0 * p0.y + wp1 * p1.y;
                float ppz = wp0 * p0.z + wp1 * p1.z;
                float ppw = wp0 * p0.w + wp1 * p1.w;
                vs.x = ce.x + mpx + ppx;  vg.x = ppx - mpx;
                vs.y = ce.y + mpy + ppy;  vg.y = ppy - mpy;
                vs.z = ce.z + mpz + ppz;  vg.z = ppz - mpz;
                vs.w = ce.w + mpw + ppw;  vg.w = ppw - mpw;
            }
            *(float4*)(sSrow + (size_t)j * SW) = vs;
            *(float4*)(sGrow + (size_t)j * SW) = vg;
        }
    }
    __syncthreads();

    // ---------------- Phase 2: horizontal stencil + quadratics ----------------
    // 1 row x 4 px per thread: 32 col groups x 16 rows = 512 threads.
    const int cg = tid & 31;         // col group 0..31
    const int r  = tid >> 5;         // row 0..15
    const int xl = cg * 4;           // local output col (window base = xl)

    float accA[4] = {0.f,0.f,0.f,0.f};
    float accB[4] = {0.f,0.f,0.f,0.f};
    float accC[4] = {0.f,0.f,0.f,0.f};

    constexpr int dM = 3 - JP;   // JM + 4
    constexpr int dP = 4 + JP;

    #pragma unroll
    for (int c = 0; c < 3; ++c) {
        const float l = (c == 0) ? 100.f : 1.f;
        const float* Sp = smS + (size_t)(c * TY + r) * SW + xl;   // window base (= pixel - 4)
        const float* Gp = smG + (size_t)(c * TY + r) * SW + xl;
        float4 a0 = *(const float4*)(Sp);
        float4 a1 = *(const float4*)(Sp + 4);
        float4 a2 = *(const float4*)(Sp + 8);
        float4 b0 = *(const float4*)(Gp);
        float4 b1 = *(const float4*)(Gp + 4);
        float4 b2 = *(const float4*)(Gp + 8);
        float sw[12] = {a0.x,a0.y,a0.z,a0.w, a1.x,a1.y,a1.z,a1.w, a2.x,a2.y,a2.z,a2.w};
        float gw[12] = {b0.x,b0.y,b0.z,b0.w, b1.x,b1.y,b1.z,b1.w, b2.x,b2.y,b2.z,b2.w};
        #pragma unroll
        for (int i = 0; i < 4; ++i) {
            float su = wp0 * sw[i + dP] + wp1 * sw[i + dP + 1]
                     - wm0 * sw[i + dM] - wm1 * sw[i + dM + 1];
            float sv = gw[i + 4]
                     + wm0 * gw[i + dM] + wm1 * gw[i + dM + 1]
                     + wp0 * gw[i + dP] + wp1 * gw[i + dP + 1];
            float a  = l * su;
            float bq = l * sv;
            accA[i] += a * a;
            accB[i] += bq * bq;
            accC[i] += a * bq;
        }
    }

    // ---------------- Output ----------------
    float* out0 = out + ((size_t)b * 3 + 0) * HW;
    float* out1 = out + ((size_t)b * 3 + 1) * HW;
    float* out2 = out + ((size_t)b * 3 + 2) * HW;
    const int gxg = bx0 + xl;
    const int gy  = by0 + r;
    const bool xint = (gxg >= 3) && (gxg + 3 <= Wd - 4);
    const bool yint = (gy >= 3) && (gy <= Hd - 4);
    const size_t o = (size_t)gy * Wd + gxg;

    if (xint && yint) {
        *(float4*)(out0 + o) = make_float4(accA[0], accA[1], accA[2], accA[3]);
        *(float4*)(out1 + o) = make_float4(accB[0], accB[1], accB[2], accB[3]);
        *(float4*)(out2 + o) = make_float4(accC[0], accC[1], accC[2], accC[3]);
    } else {
        #pragma unroll
        for (int i = 0; i < 4; ++i) {
            int gx = gxg + i;
            float A = accA[i], Bv = accB[i], Cv = accC[i];
            if (!(yint && gx >= 3 && gx <= Wd - 4)) {
                exact_pixel(xb, s, gx, gy, A, Bv, Cv);
            }
            out0[o + i] = A;
            out1[o + i] = Bv;
            out2[o + i] = Cv;
        }
    }
}

__global__ __launch_bounds__(NTH, 2)
void st9_kernel(const float* __restrict__ x, const float* __restrict__ sigma,
                float* __restrict__ out) {
    extern __shared__ float sm[];
    float* smS = sm;
    float* smG = sm + SMEM_FLOATS;

    const int b   = blockIdx.z;
    const int bx0 = blockIdx.x * TX;
    const int by0 = blockIdx.y * TY;
    const int tid = threadIdx.x;

    const float s = __ldg(&sigma[b]);
    const int jp = clampi((int)floorf(s), 0, 2);
    const float* xb = x + (size_t)b * 3 * HW;

    if (jp == 0)      run_tile<0>(xb, s, smS, smG, out, b, bx0, by0, tid);
    else if (jp == 1) run_tile<1>(xb, s, smS, smG, out, b, bx0, by0, tid);
    else              run_tile<2>(xb, s, smS, smG, out, b, bx0, by0, tid);
}

extern "C" void kernel_launch(void* const* d_in, const int* in_sizes, int n_in,
                              void* d_out, int out_size) {
    const float* x     = (const float*)d_in[0];
    const float* sigma = (const float*)d_in[1];
    float* out = (float*)d_out;
    int B = in_sizes[1];

    static_assert(SMEM_BYTES == 52224, "smem size");
    cudaFuncSetAttribute(st9_kernel, cudaFuncAttributeMaxDynamicSharedMemorySize, SMEM_BYTES);

    dim3 grid(Wd / TX, Hd / TY, B);                 // (8, 64, 4) = 2048 blocks
    st9_kernel<<<grid, NTH, SMEM_BYTES>>>(x, sigma, out);
}

// round 10
// speedup vs baseline: 2.0441x; 1.2671x over previous
#include <cuda_runtime.h>
#include <cstdint>

// StructureTensorEffect, B=4, C=3, H=W=1024.
// Separable: s_u = Gx*Sy, s_v = Sx*Gy, per-batch-constant stencils.
// sigma in [0.5,2.5) => JP = floor(sigma) in {0,1,2}; templated on JP.
//
// R10 = R2 + f32x2 packed math (phase-1 vertical + phase-2 quadratics),
// 32-bit indexing, per-column-clamped halo (right/bottom borders exact via
// the separable path; exact_pixel fallback only for x<=JP or y<=JP).

#define Wd 1024
#define Hd 1024
#define TX 128
#define TY 16
#define HX 4
#define SW (TX + 2*HX)            // 136 floats per smem row
#define NTH 256
#define NSTRIP (SW/4)             // 34 float4 strips
#define CHUNK 8
#define NCHUNK (TY/CHUNK)         // 2
#define NVTASK (NSTRIP*NCHUNK*3)  // 204
#define HW (Hd*Wd)
#define SMEM_FLOATS (3*TY*SW)     // per array
#define SMEM_BYTES (2*SMEM_FLOATS*4)

// ---- f32x2 packed helpers (Blackwell FFMA2 path, PTX-only) ----
__device__ __forceinline__ uint64_t pk(float lo, float hi) {
    uint64_t r;
    asm("mov.b64 %0, {%1, %2};" : "=l"(r)
        : "r"(__float_as_uint(lo)), "r"(__float_as_uint(hi)));
    return r;
}
__device__ __forceinline__ void upk(uint64_t v, float& lo, float& hi) {
    uint32_t a, b;
    asm("mov.b64 {%0, %1}, %2;" : "=r"(a), "=r"(b) : "l"(v));
    lo = __uint_as_float(a); hi = __uint_as_float(b);
}
__device__ __forceinline__ uint64_t mul2(uint64_t a, uint64_t b) {
    uint64_t r; asm("mul.rn.f32x2 %0, %1, %2;" : "=l"(r) : "l"(a), "l"(b)); return r;
}
__device__ __forceinline__ uint64_t add2(uint64_t a, uint64_t b) {
    uint64_t r; asm("add.rn.f32x2 %0, %1, %2;" : "=l"(r) : "l"(a), "l"(b)); return r;
}
__device__ __forceinline__ uint64_t fma2(uint64_t a, uint64_t b, uint64_t c) {
    uint64_t r; asm("fma.rn.f32x2 %0, %1, %2, %3;" : "=l"(r) : "l"(a), "l"(b), "l"(c)); return r;
}
#define NEG1_2 0xBF800000BF800000ULL   // (-1.f, -1.f)
#define C100_2 0x42C8000042C80000ULL   // (100.f, 100.f)

__device__ __forceinline__ int clampi(int v, int lo, int hi) {
    return min(max(v, lo), hi);
}

// Exact per-pixel path replicating reference clip semantics (left/top only).
__device__ __noinline__ void exact_pixel(const float* __restrict__ xb, float s,
                                         int gx, int gy,
                                         float& A, float& Bv, float& Cv) {
    const float OU[8] = {-1.f,-1.f,-1.f, 0.f, 0.f, 1.f, 1.f, 1.f};
    const float OV[8] = {-1.f, 0.f, 1.f,-1.f, 1.f,-1.f, 0.f, 1.f};
    const float KU[8] = {-0.25f,-0.5f,-0.25f, 0.f, 0.f, 0.25f, 0.5f, 0.25f};
    const float KV[8] = {-0.25f, 0.f, 0.25f,-0.5f, 0.5f,-0.25f, 0.f, 0.25f};
    float su[3] = {0.f,0.f,0.f}, sv[3] = {0.f,0.f,0.f};
    #pragma unroll
    for (int t = 0; t < 8; ++t) {
        float px = (float)gx + OU[t] * s;
        float py = (float)gy + OV[t] * s;
        float x0f = floorf(px), y0f = floorf(py);
        float fx = px - x0f, fy = py - y0f;
        int x0 = clampi((int)x0f, 0, Wd - 1);
        int x1 = min(x0 + 1, Wd - 1);
        int y0 = clampi((int)y0f, 0, Hd - 1);
        int y1 = min(y0 + 1, Hd - 1);
        float w00 = (1.f - fx) * (1.f - fy);
        float w01 = fx * (1.f - fy);
        float w10 = (1.f - fx) * fy;
        float w11 = fx * fy;
        #pragma unroll
        for (int c = 0; c < 3; ++c) {
            const float* p = xb + c * HW;
            float bil = w00 * __ldg(&p[y0 * Wd + x0]) + w01 * __ldg(&p[y0 * Wd + x1])
                      + w10 * __ldg(&p[y1 * Wd + x0]) + w11 * __ldg(&p[y1 * Wd + x1]);
            su[c] += KU[t] * bil;
            sv[c] += KV[t] * bil;
        }
    }
    A = 0.f; Bv = 0.f; Cv = 0.f;
    #pragma unroll
    for (int c = 0; c < 3; ++c) {
        float l = (c == 0) ? 100.f : 1.f;
        float a = su[c] * l, b = sv[c] * l;
        A += a * a; Bv += b * b; Cv += a * b;
    }
}

struct P2 { uint64_t lo, hi; };   // packed float4

template<int JP>
__device__ __forceinline__ void run_tile(const float* __restrict__ xb, float s,
                                         float* __restrict__ smS,
                                         float* __restrict__ smG,
                                         float* __restrict__ out,
                                         int b, int bx0, int by0, int tid) {
    const float fp  = s - (float)JP;
    const float wp0 = 0.5f * (1.f - fp);
    const float wp1 = 0.5f * fp;
    const float wm0 = wp1;
    const float wm1 = wp0;

    // ---------------- Phase 1: vertical stencil (f32x2) -> smem ----------------
    if (tid < NVTASK) {
        const int c     = tid / (NSTRIP * NCHUNK);
        const int rem   = tid - c * (NSTRIP * NCHUNK);
        const int chunk = rem / NSTRIP;
        const int strip = rem - chunk * NSTRIP;

        const float* plane = xb + c * HW;
        const int gxu  = bx0 - HX + strip * 4;            // unclamped
        const bool edge = (gxu < 0) || (gxu > Wd - 4);
        const int cx0 = clampi(gxu + 0, 0, Wd - 1);
        const int cx1 = clampi(gxu + 1, 0, Wd - 1);
        const int cx2 = clampi(gxu + 2, 0, Wd - 1);
        const int cx3 = clampi(gxu + 3, 0, Wd - 1);
        const int ybase = by0 + chunk * CHUNK;

        const uint64_t Wm0 = pk(wm0, wm0), Wm1 = pk(wm1, wm1);
        const uint64_t Wp0 = pk(wp0, wp0), Wp1 = pk(wp1, wp1);

        auto ldrow = [&](int yy) -> P2 {
            const int yo = clampi(yy, 0, Hd - 1) * Wd;
            float4 v;
            if (!edge) {
                v = __ldg((const float4*)(plane + yo + gxu));
            } else {
                v.x = __ldg(plane + yo + cx0);
                v.y = __ldg(plane + yo + cx1);
                v.z = __ldg(plane + yo + cx2);
                v.w = __ldg(plane + yo + cx3);
            }
            P2 p; p.lo = pk(v.x, v.y); p.hi = pk(v.z, v.w);
            return p;
        };

        constexpr int WIN = 2 * JP + 3;
        P2 win[WIN];
        #pragma unroll
        for (int r = -JP - 1; r <= JP; ++r)
            win[r + JP + 1] = ldrow(ybase + r);

        float* sSrow = smS + (c * TY + chunk * CHUNK) * SW + strip * 4;
        float* sGrow = smG + (c * TY + chunk * CHUNK) * SW + strip * 4;

        #pragma unroll
        for (int j = 0; j < CHUNK; ++j) {
            win[(j + 2 * JP + 2) % WIN] = ldrow(ybase + j + JP + 1);

            P2 m0 = win[(j)              % WIN];
            P2 m1 = win[(j + 1)          % WIN];
            P2 ce = win[(j + JP + 1)     % WIN];
            P2 p0 = win[(j + 2 * JP + 1) % WIN];
            P2 p1 = win[(j + 2 * JP + 2) % WIN];

            uint64_t mpl = fma2(Wm1, m1.lo, mul2(Wm0, m0.lo));
            uint64_t mph = fma2(Wm1, m1.hi, mul2(Wm0, m0.hi));
            uint64_t ppl = fma2(Wp1, p1.lo, mul2(Wp0, p0.lo));
            uint64_t pph = fma2(Wp1, p1.hi, mul2(Wp0, p0.hi));
            uint64_t vsl = add2(ce.lo, add2(mpl, ppl));
            uint64_t vsh = add2(ce.hi, add2(mph, pph));
            uint64_t vgl = fma2(mpl, NEG1_2, ppl);       // pp - mp
            uint64_t vgh = fma2(mph, NEG1_2, pph);

            *(ulonglong2*)(sSrow + j * SW) = make_ulonglong2(vsl, vsh);
            *(ulonglong2*)(sGrow + j * SW) = make_ulonglong2(vgl, vgh);
        }
    }
    __syncthreads();

    // ---------------- Phase 2: horizontal stencil + packed quadratics ----------
    const int tx5 = tid & 31;        // col group
    const int tyh = tid >> 5;        // 0..7
    const int xl  = tx5 * 4;
    const int r0  = tyh * 2;

    uint64_t qA[2][2], qB[2][2], qC[2][2];
    #pragma unroll
    for (int rr = 0; rr < 2; ++rr)
        #pragma unroll
        for (int k = 0; k < 2; ++k) { qA[rr][k] = 0; qB[rr][k] = 0; qC[rr][k] = 0; }

    constexpr int dM = 3 - JP;
    constexpr int dP = 4 + JP;

    #pragma unroll
    for (int c = 0; c < 3; ++c) {
        #pragma unroll
        for (int rr = 0; rr < 2; ++rr) {
            const int lr = r0 + rr;
            const float* Sp = smS + (c * TY + lr) * SW + xl;
            const float* Gp = smG + (c * TY + lr) * SW + xl;
            float4 a0 = *(const float4*)(Sp);
            float4 a1 = *(const float4*)(Sp + 4);
            float4 a2 = *(const float4*)(Sp + 8);
            float4 b0 = *(const float4*)(Gp);
            float4 b1 = *(const float4*)(Gp + 4);
            float4 b2 = *(const float4*)(Gp + 8);
            float sw[12] = {a0.x,a0.y,a0.z,a0.w, a1.x,a1.y,a1.z,a1.w, a2.x,a2.y,a2.z,a2.w};
            float gw[12] = {b0.x,b0.y,b0.z,b0.w, b1.x,b1.y,b1.z,b1.w, b2.x,b2.y,b2.z,b2.w};
            float su[4], sv[4];
            #pragma unroll
            for (int i = 0; i < 4; ++i) {
                su[i] = wp0 * sw[i + dP] + wp1 * sw[i + dP + 1]
                      - wm0 * sw[i + dM] - wm1 * sw[i + dM + 1];
                sv[i] = gw[i + 4]
                      + wm0 * gw[i + dM] + wm1 * gw[i + dM + 1]
                      + wp0 * gw[i + dP] + wp1 * gw[i + dP + 1];
            }
            uint64_t p01 = pk(su[0], su[1]), p23 = pk(su[2], su[3]);
            uint64_t q01 = pk(sv[0], sv[1]), q23 = pk(sv[2], sv[3]);
            if (c == 0) {                   // lum=100 channel; others lum=1
                p01 = mul2(p01, C100_2); p23 = mul2(p23, C100_2);
                q01 = mul2(q01, C100_2); q23 = mul2(q23, C100_2);
            }
            qA[rr][0] = fma2(p01, p01, qA[rr][0]);
            qA[rr][1] = fma2(p23, p23, qA[rr][1]);
            qB[rr][0] = fma2(q01, q01, qB[rr][0]);
            qB[rr][1] = fma2(q23, q23, qB[rr][1]);
            qC[rr][0] = fma2(p01, q01, qC[rr][0]);
            qC[rr][1] = fma2(p23, q23, qC[rr][1]);
        }
    }

    // ---------------- Output ----------------
    float* out0 = out + (b * 3 + 0) * HW;
    float* out1 = out + (b * 3 + 1) * HW;
    float* out2 = out + (b * 3 + 2) * HW;
    const int gxg = bx0 + xl;

    #pragma unroll
    for (int rr = 0; rr < 2; ++rr) {
        const int gy = by0 + r0 + rr;
        const int o  = gy * Wd + gxg;
        float A[4], Bv[4], Cv[4];
        upk(qA[rr][0], A[0], A[1]);   upk(qA[rr][1], A[2], A[3]);
        upk(qB[rr][0], Bv[0], Bv[1]); upk(qB[rr][1], Bv[2], Bv[3]);
        upk(qC[rr][0], Cv[0], Cv[1]); upk(qC[rr][1], Cv[2], Cv[3]);

        // Right/bottom are exact via clamped taps; fallback only left/top.
        if (gxg >= 4 && gy > JP) {
            *(float4*)(out0 + o) = make_float4(A[0], A[1], A[2], A[3]);
            *(float4*)(out1 + o) = make_float4(Bv[0], Bv[1], Bv[2], Bv[3]);
            *(float4*)(out2 + o) = make_float4(Cv[0], Cv[1], Cv[2], Cv[3]);
        } else {
            #pragma unroll
            for (int i = 0; i < 4; ++i) {
                int gx = gxg + i;
                float a = A[i], bq = Bv[i], cq = Cv[i];
                if (gx <= JP || gy <= JP) {
                    exact_pixel(xb, s, gx, gy, a, bq, cq);
                }
                out0[o + i] = a;
                out1[o + i] = bq;
                out2[o + i] = cq;
            }
        }
    }
}

__global__ __launch_bounds__(NTH, 3)
void st10_kernel(const float* __restrict__ x, const float* __restrict__ sigma,
                 float* __restrict__ out) {
    extern __shared__ float sm[];
    float* smS = sm;
    float* smG = sm + SMEM_FLOATS;

    const int b   = blockIdx.z;
    const int bx0 = blockIdx.x * TX;
    const int by0 = blockIdx.y * TY;
    const int tid = threadIdx.x;

    const float s = __ldg(&sigma[b]);
    const int jp = clampi((int)floorf(s), 0, 2);
    const float* xb = x + b * 3 * HW;

    if (jp == 0)      run_tile<0>(xb, s, smS, smG, out, b, bx0, by0, tid);
    else if (jp == 1) run_tile<1>(xb, s, smS, smG, out, b, bx0, by0, tid);
    else              run_tile<2>(xb, s, smS, smG, out, b, bx0, by0, tid);
}

extern "C" void kernel_launch(void* const* d_in, const int* in_sizes, int n_in,
                              void* d_out, int out_size) {
    const float* x     = (const float*)d_in[0];
    const float* sigma = (const float*)d_in[1];
    float* out = (float*)d_out;
    int B = in_sizes[1];

    static_assert(SMEM_BYTES == 52224, "smem size");
    cudaFuncSetAttribute(st10_kernel, cudaFuncAttributeMaxDynamicSharedMemorySize, SMEM_BYTES);

    dim3 grid(Wd / TX, Hd / TY, B);
    st10_kernel<<<grid, NTH, SMEM_BYTES>>>(x, sigma, out);
}